// round 9
// baseline (speedup 1.0000x reference)
#include <cuda_runtime.h>
#include <cstdint>

#define IMG_H 512
#define IMG_W 512
#define TILE_W 64
#define TILE_H 16
#define HALO 5
#define IN_W (TILE_W + 2*HALO)   // 74 logical halo columns
#define IN_H (TILE_H + 2*HALO)   // 26
#define SSTRIDE 80               // s1/s2 row stride (floats)
#define S2STRIDE 82              // mid plane stride in float2 units (bank-skewed)
#define NTHREADS 256
#define MM_PART 512              // blocks doing min/max partials (< wave-1 residency 888)

typedef unsigned long long ull;

// Normalized Gaussian taps: g[k] = exp(-(k - 11/2)^2 / (2*1.5^2)) / sum, k=0..10.
// Center at 5.5 => ASYMMETRIC: w[k] == w[11-k] for k>=1, w[0] unique smallest.
__host__ __device__ __forceinline__ constexpr float Wc(int k) {
    return (k == 0)            ? 3.2030000e-04f
         : (k == 1 || k == 10) ? 2.9556400e-03f
         : (k == 2 || k == 9 ) ? 1.7487660e-02f
         : (k == 3 || k == 8 ) ? 6.6342400e-02f
         : (k == 4 || k == 7 ) ? 1.6137290e-01f
         :                       2.5168140e-01f;   // k == 5 || k == 6
}
__host__ __device__ __forceinline__ constexpr int Widx(int k) {
    return (k == 0)            ? 0
         : (k == 1 || k == 10) ? 1
         : (k == 2 || k == 9 ) ? 2
         : (k == 3 || k == 8 ) ? 3
         : (k == 4 || k == 7 ) ? 4
         :                       5;
}

// ---- f32x2 packed helpers ----
__device__ __forceinline__ ull pack2(float lo, float hi) {
    ull r;
    asm("mov.b64 %0, {%1, %2};" : "=l"(r) : "f"(lo), "f"(hi));
    return r;
}
__device__ __forceinline__ void unpack2(float& lo, float& hi, ull v) {
    asm("mov.b64 {%0, %1}, %2;" : "=f"(lo), "=f"(hi) : "l"(v));
}
__device__ __forceinline__ ull fma2(ull a, ull b, ull c) {
    ull d;
    asm("fma.rn.f32x2 %0, %1, %2, %3;" : "=l"(d) : "l"(a), "l"(b), "l"(c));
    return d;
}

// ---------------- fused min/max state (all inside the one kernel) ----------------

__device__ float2   g_part[MM_PART];
__device__ unsigned g_count = 0;   // arrival counter for partials (reset each launch)
__device__ unsigned g_done  = 0;   // end-of-kernel counter (resets g_flag)
__device__ unsigned g_flag  = 0;   // 1 when g_mm is valid
__device__ float    g_mm[2];       // [0]=min, [1]=max

// ---------------- fused separable SSIM kernel ----------------
//
// One block = 64x16 output tile. smem = 36.75KB dynamic -> 6 blocks/SM.
// First MM_PART blocks ALSO compute global min/max partials of img1 up front;
// last arriver reduces and releases g_flag. Everyone spins (tid0) before the
// SSIM formula (flag is set long before due to overlap).
// Field pairs travel as f32x2: plane01 = (mu1, mu2), plane23 = (xx+yy, xy).
// Phase 1: cp.async 16B zfill halo load.
// Phase 2: vertical 11-tap conv, FFMA2 scatter into 2 float2 planes.
// Phase 3: plane-split 8-wide horizontal conv + shfl pair-exchange + formula.

__global__ void __launch_bounds__(NTHREADS, 6)
ssim_kernel(const float* __restrict__ img1, const float* __restrict__ img2,
            float* __restrict__ out, int n4)
{
    extern __shared__ float smem[];
    float* s1 = smem;                          // IN_H * SSTRIDE floats
    float* s2 = smem + IN_H * SSTRIDE;
    ull* mid01 = reinterpret_cast<ull*>(smem + 2 * IN_H * SSTRIDE);   // TILE_H * S2STRIDE
    ull* mid23 = mid01 + TILE_H * S2STRIDE;

    __shared__ float slo[8], shi[8];
    __shared__ int s_last;

    const int bx = blockIdx.x, by = blockIdx.y, bz = blockIdx.z;
    const int tid = threadIdx.x;
    const int flat = bx + (int)gridDim.x * (by + (int)gridDim.y * bz);
    const int nblocks = (int)(gridDim.x * gridDim.y * gridDim.z);
    const size_t base = (size_t)bz * (IMG_H * IMG_W);
    const float* p1 = img1 + base;
    const float* p2 = img2 + base;

    // ---- Phase 0: min/max partials (first MM_PART blocks only) ----
    if (flat < MM_PART) {
        float lo =  3.402823466e38f;
        float hi = -3.402823466e38f;
        const float4* x4 = reinterpret_cast<const float4*>(img1);
        for (int i = flat * NTHREADS + tid; i < n4; i += MM_PART * NTHREADS) {
            float4 v = __ldg(x4 + i);
            lo = fminf(lo, fminf(fminf(v.x, v.y), fminf(v.z, v.w)));
            hi = fmaxf(hi, fmaxf(fmaxf(v.x, v.y), fmaxf(v.z, v.w)));
        }
        #pragma unroll
        for (int s = 16; s > 0; s >>= 1) {
            lo = fminf(lo, __shfl_xor_sync(0xFFFFFFFFu, lo, s));
            hi = fmaxf(hi, __shfl_xor_sync(0xFFFFFFFFu, hi, s));
        }
        int w = tid >> 5, l = tid & 31;
        if (l == 0) { slo[w] = lo; shi[w] = hi; }
        __syncthreads();
        if (tid == 0) {
            for (int i = 1; i < 8; i++) { lo = fminf(lo, slo[i]); hi = fmaxf(hi, shi[i]); }
            g_part[flat] = make_float2(lo, hi);
            __threadfence();
            unsigned t = atomicAdd(&g_count, 1u);
            s_last = (t == MM_PART - 1) ? 1 : 0;
        }
        __syncthreads();
        if (s_last) {
            __threadfence();
            float2 pa = g_part[tid];
            float2 pb = g_part[tid + 256];
            lo = fminf(pa.x, pb.x);
            hi = fmaxf(pa.y, pb.y);
            #pragma unroll
            for (int s = 16; s > 0; s >>= 1) {
                lo = fminf(lo, __shfl_xor_sync(0xFFFFFFFFu, lo, s));
                hi = fmaxf(hi, __shfl_xor_sync(0xFFFFFFFFu, hi, s));
            }
            if (l == 0) { slo[w] = lo; shi[w] = hi; }
            __syncthreads();
            if (tid == 0) {
                for (int i = 1; i < 8; i++) { lo = fminf(lo, slo[i]); hi = fmaxf(hi, shi[i]); }
                g_mm[0] = lo;
                g_mm[1] = hi;
                g_count = 0;                 // reset for next replay
                __threadfence();
                atomicExch(&g_flag, 1u);     // release
            }
        }
        __syncthreads();
    }

    // packed duplicated weights
    ull Wp[6];
    #pragma unroll
    for (int j = 0; j < 6; j++) {
        const float wv = (j == 0) ? Wc(0) : (j == 1) ? Wc(1) : (j == 2) ? Wc(2)
                       : (j == 3) ? Wc(3) : (j == 4) ? Wc(4) : Wc(5);
        Wp[j] = pack2(wv, wv);
    }

    // ---- Phase 1: cp.async halo load, zero-fill OOB granules ----
    const int gx_base = bx * TILE_W - 8;    // 16B-aligned; granules fully in/out
    const int gy_base = by * TILE_H - HALO;
    for (int idx = tid; idx < IN_H * 20; idx += NTHREADS) {
        int r  = idx / 20;
        int c4 = idx - r * 20;
        int gy = gy_base + r;
        int gx = gx_base + c4 * 4;
        bool ok = ((unsigned)gy < (unsigned)IMG_H) && ((unsigned)gx < (unsigned)IMG_W);
        int cgy = min(max(gy, 0), IMG_H - 1);
        int cgx = min(max(gx, 0), IMG_W - 4);
        const float* g1 = p1 + cgy * IMG_W + cgx;
        const float* g2 = p2 + cgy * IMG_W + cgx;
        unsigned d1 = (unsigned)__cvta_generic_to_shared(s1 + r * SSTRIDE + c4 * 4);
        unsigned d2 = (unsigned)__cvta_generic_to_shared(s2 + r * SSTRIDE + c4 * 4);
        int sz = ok ? 16 : 0;
        asm volatile("cp.async.cg.shared.global [%0], [%1], 16, %2;\n"
                     :: "r"(d1), "l"(g1), "r"(sz));
        asm volatile("cp.async.cg.shared.global [%0], [%1], 16, %2;\n"
                     :: "r"(d2), "l"(g2), "r"(sz));
    }
    asm volatile("cp.async.commit_group;\n");
    asm volatile("cp.async.wait_group 0;\n");
    __syncthreads();

    // ---- Phase 2: vertical conv, paired-field FFMA2 scatter ----
    for (int task = tid; task < IN_W * (TILE_H / 4); task += NTHREADS) {
        int c  = task % IN_W;              // logical column 0..73
        int j0 = (task / IN_W) * 4;
        const float* col1 = s1 + j0 * SSTRIDE + (c + 3);
        const float* col2 = s2 + j0 * SSTRIDE + (c + 3);

        ull A01[4], A23[4];
        #pragma unroll
        for (int m = 0; m < 4; m++) { A01[m] = 0ull; A23[m] = 0ull; }

        #pragma unroll
        for (int r = 0; r < 14; r++) {
            float x = col1[r * SSTRIDE];
            float y = col2[r * SSTRIDE];
            float xy   = x * y;
            float xxyy = fmaf(x, x, y * y);
            ull p01 = pack2(x, y);
            ull p23 = pack2(xxyy, xy);
            #pragma unroll
            for (int m = 0; m < 4; m++) {
                const int k = r - m;
                if (k >= 0 && k < 11) {         // compile-time resolved
                    A01[m] = fma2(p01, Wp[Widx(k)], A01[m]);
                    A23[m] = fma2(p23, Wp[Widx(k)], A23[m]);
                }
            }
        }
        #pragma unroll
        for (int m = 0; m < 4; m++) {
            int o = (j0 + m) * S2STRIDE + c;
            mid01[o] = A01[m];
            mid23[o] = A23[m];
        }
    }
    __syncthreads();

    // ---- Phase 3: plane-split horizontal conv (8 outputs per thread pair) ----
    const int p   = tid & 1;            // plane: 0 = (mu1,mu2), 1 = (xx+yy, xy)
    const int g   = (tid >> 1) & 7;     // 8-col group
    const int row = tid >> 4;           // 0..15
    const int c0  = g * 8;

    ull acc[8];
    #pragma unroll
    for (int i = 0; i < 8; i++) acc[i] = 0ull;
    {
        const ull* plane = p ? mid23 : mid01;
        const ulonglong2* ptr = reinterpret_cast<const ulonglong2*>(
            plane + row * S2STRIDE + c0);
        #pragma unroll
        for (int q = 0; q < 9; q++) {
            ulonglong2 u = ptr[q];
            #pragma unroll
            for (int h = 0; h < 2; h++) {
                const int j = 2 * q + h;
                const ull e = h ? u.y : u.x;
                #pragma unroll
                for (int i = 0; i < 8; i++) {
                    const int k = j - i;
                    if (k >= 0 && k < 11)
                        acc[i] = fma2(e, Wp[Widx(k)], acc[i]);
                }
            }
        }
    }

    // pair exchange: thread p gets the OTHER plane's accs for its 4 outputs
    ull r4[4];
    #pragma unroll
    for (int j = 0; j < 4; j++) {
        ull send = (p == 0) ? acc[4 + j] : acc[j];
        r4[j] = __shfl_xor_sync(0xFFFFFFFFu, send, 1);
    }

    // wait for global min/max (normally already set)
    if (tid == 0) {
        while (*((volatile unsigned*)&g_flag) == 0u) __nanosleep(64);
    }
    __syncthreads();
    float mn = *((volatile float*)&g_mm[0]);
    float mx = *((volatile float*)&g_mm[1]);
    float L = mx - mn;
    if (L == 0.0f) L = 5.0f;
    const float c1v = 0.01f * L, c2v = 0.03f * L;
    const float C1 = c1v * c1v, C2 = c2v * c2v;

    float o4[4];
    #pragma unroll
    for (int i = 0; i < 4; i++) {
        ull mu_acc = (p == 0) ? acc[i] : r4[i];
        ull sq_acc = (p == 0) ? r4[i] : acc[4 + i];
        float mu1, mu2, sqc, xyc;
        unpack2(mu1, mu2, mu_acc);
        unpack2(sqc, xyc, sq_acc);
        float mu1s = mu1 * mu1, mu2s = mu2 * mu2, m12 = mu1 * mu2;
        float sqsum = sqc - mu1s - mu2s;   // sigma1_sq + sigma2_sq
        float s12   = xyc - m12;           // sigma12
        float num = (2.f * m12 + C1) * (2.f * s12 + C2);
        float den = (mu1s + mu2s + C1) * (sqsum + C2);
        o4[i] = __fdividef(num, den);
    }

    const int gy = by * TILE_H + row;
    const int gx = bx * TILE_W + c0 + 4 * p;
    float4* po = reinterpret_cast<float4*>(out + base + gy * IMG_W + gx);
    po[0] = make_float4(o4[0], o4[1], o4[2], o4[3]);

    // ---- epilogue: last block resets g_flag/g_done for the next graph replay ----
    if (tid == 0) {
        unsigned d = atomicAdd(&g_done, 1u);
        if (d == (unsigned)(nblocks - 1)) {
            g_flag = 0u;
            g_done = 0u;
        }
    }
}

// ---------------- launch ----------------

extern "C" void kernel_launch(void* const* d_in, const int* in_sizes, int n_in,
                              void* d_out, int out_size)
{
    const float* img1 = (const float*)d_in[0];
    const float* img2 = (const float*)d_in[1];
    float* out = (float*)d_out;
    const int n = in_sizes[0];
    const int batch = n / (IMG_H * IMG_W);

    const int smem_bytes = (2 * IN_H * SSTRIDE) * (int)sizeof(float)
                         + (2 * TILE_H * S2STRIDE) * (int)sizeof(ull);
    cudaFuncSetAttribute(ssim_kernel, cudaFuncAttributeMaxDynamicSharedMemorySize, smem_bytes);

    dim3 grid(IMG_W / TILE_W, IMG_H / TILE_H, batch);
    ssim_kernel<<<grid, NTHREADS, smem_bytes>>>(img1, img2, out, n / 4);
}

// round 10
// speedup vs baseline: 1.0598x; 1.0598x over previous
#include <cuda_runtime.h>
#include <cstdint>

#define IMG_H 512
#define IMG_W 512
#define TILE_W 64
#define TILE_H 16
#define HALO 5
#define IN_W (TILE_W + 2*HALO)   // 74 logical halo columns
#define IN_H (TILE_H + 2*HALO)   // 26
#define SSTRIDE 80               // s1/s2 row stride (floats)
#define S2STRIDE 82              // mid plane stride in float2 units (bank-skewed)
#define NTHREADS 256

typedef unsigned long long ull;

// Normalized Gaussian taps: g[k] = exp(-(k - 11/2)^2 / (2*1.5^2)) / sum, k=0..10.
// Center at 5.5 => ASYMMETRIC: w[k] == w[11-k] for k>=1, w[0] unique smallest.
__host__ __device__ __forceinline__ constexpr float Wc(int k) {
    return (k == 0)            ? 3.2030000e-04f
         : (k == 1 || k == 10) ? 2.9556400e-03f
         : (k == 2 || k == 9 ) ? 1.7487660e-02f
         : (k == 3 || k == 8 ) ? 6.6342400e-02f
         : (k == 4 || k == 7 ) ? 1.6137290e-01f
         :                       2.5168140e-01f;   // k == 5 || k == 6
}
__host__ __device__ __forceinline__ constexpr int Widx(int k) {
    return (k == 0)            ? 0
         : (k == 1 || k == 10) ? 1
         : (k == 2 || k == 9 ) ? 2
         : (k == 3 || k == 8 ) ? 3
         : (k == 4 || k == 7 ) ? 4
         :                       5;
}

// ---- f32x2 packed helpers ----
__device__ __forceinline__ ull pack2(float lo, float hi) {
    ull r;
    asm("mov.b64 %0, {%1, %2};" : "=l"(r) : "f"(lo), "f"(hi));
    return r;
}
__device__ __forceinline__ void unpack2(float& lo, float& hi, ull v) {
    asm("mov.b64 {%0, %1}, %2;" : "=f"(lo), "=f"(hi) : "l"(v));
}
__device__ __forceinline__ ull fma2(ull a, ull b, ull c) {
    ull d;
    asm("fma.rn.f32x2 %0, %1, %2, %3;" : "=l"(d) : "l"(a), "l"(b), "l"(c));
    return d;
}

// ---------------- global min/max of img1 (encoded atomics, no init kernel) ----------------
// Sentinels are restored by ssim_kernel's last-finishing block each launch.

__device__ unsigned g_minmax[2] = { 0xFFFFFFFFu, 0u };   // [0]=min slot, [1]=max slot
__device__ unsigned g_done = 0;

__device__ __forceinline__ unsigned enc_f(float f) {
    unsigned u = __float_as_uint(f);
    return (u & 0x80000000u) ? ~u : (u | 0x80000000u);
}
__device__ __forceinline__ float dec_f(unsigned u) {
    return (u & 0x80000000u) ? __uint_as_float(u ^ 0x80000000u) : __uint_as_float(~u);
}

__global__ void minmax_k(const float4* __restrict__ x, int n4) {
    float lo =  3.402823466e38f;
    float hi = -3.402823466e38f;
    for (int i = blockIdx.x * blockDim.x + threadIdx.x; i < n4; i += gridDim.x * blockDim.x) {
        float4 v = x[i];
        lo = fminf(lo, fminf(fminf(v.x, v.y), fminf(v.z, v.w)));
        hi = fmaxf(hi, fmaxf(fmaxf(v.x, v.y), fmaxf(v.z, v.w)));
    }
    #pragma unroll
    for (int s = 16; s > 0; s >>= 1) {
        lo = fminf(lo, __shfl_xor_sync(0xFFFFFFFFu, lo, s));
        hi = fmaxf(hi, __shfl_xor_sync(0xFFFFFFFFu, hi, s));
    }
    __shared__ float slo[8], shi[8];
    int w = threadIdx.x >> 5, l = threadIdx.x & 31;
    if (l == 0) { slo[w] = lo; shi[w] = hi; }
    __syncthreads();
    if (threadIdx.x == 0) {
        int nw = blockDim.x >> 5;
        for (int i = 1; i < nw; i++) { lo = fminf(lo, slo[i]); hi = fmaxf(hi, shi[i]); }
        atomicMin(&g_minmax[0], enc_f(lo));
        atomicMax(&g_minmax[1], enc_f(hi));
    }
}

// ---------------- fused separable SSIM kernel ----------------
//
// One block = 64x16 output tile. smem = 36.9KB dynamic -> 6 blocks/SM.
// Field pairs travel as f32x2: plane01 = (mu1, mu2), plane23 = (xx+yy, xy).
// Phase 1: cp.async 16B zfill halo load.
// Phase 2: vertical 11-tap conv, FFMA2 scatter into 2 float2 planes.
// Phase 3: plane-split 8-wide horizontal conv + shfl pair-exchange + formula.
// Epilogue: last block restores g_minmax sentinels for the next graph replay.

__global__ void __launch_bounds__(NTHREADS, 6)
ssim_kernel(const float* __restrict__ img1, const float* __restrict__ img2,
            float* __restrict__ out)
{
    extern __shared__ float smem[];
    float* s1 = smem;                          // IN_H * SSTRIDE floats
    float* s2 = smem + IN_H * SSTRIDE;
    ull* mid01 = reinterpret_cast<ull*>(smem + 2 * IN_H * SSTRIDE);   // TILE_H * S2STRIDE
    ull* mid23 = mid01 + TILE_H * S2STRIDE;

    const int bx = blockIdx.x, by = blockIdx.y, bz = blockIdx.z;
    const int tid = threadIdx.x;
    const int nblocks = (int)(gridDim.x * gridDim.y * gridDim.z);
    const size_t base = (size_t)bz * (IMG_H * IMG_W);
    const float* p1 = img1 + base;
    const float* p2 = img2 + base;

    // packed duplicated weights
    ull Wp[6];
    #pragma unroll
    for (int j = 0; j < 6; j++) {
        const float wv = (j == 0) ? Wc(0) : (j == 1) ? Wc(1) : (j == 2) ? Wc(2)
                       : (j == 3) ? Wc(3) : (j == 4) ? Wc(4) : Wc(5);
        Wp[j] = pack2(wv, wv);
    }

    // ---- Phase 1: cp.async halo load, zero-fill OOB granules ----
    const int gx_base = bx * TILE_W - 8;    // 16B-aligned; granules fully in/out
    const int gy_base = by * TILE_H - HALO;
    for (int idx = tid; idx < IN_H * 20; idx += NTHREADS) {
        int r  = idx / 20;
        int c4 = idx - r * 20;
        int gy = gy_base + r;
        int gx = gx_base + c4 * 4;
        bool ok = ((unsigned)gy < (unsigned)IMG_H) && ((unsigned)gx < (unsigned)IMG_W);
        int cgy = min(max(gy, 0), IMG_H - 1);
        int cgx = min(max(gx, 0), IMG_W - 4);
        const float* g1 = p1 + cgy * IMG_W + cgx;
        const float* g2 = p2 + cgy * IMG_W + cgx;
        unsigned d1 = (unsigned)__cvta_generic_to_shared(s1 + r * SSTRIDE + c4 * 4);
        unsigned d2 = (unsigned)__cvta_generic_to_shared(s2 + r * SSTRIDE + c4 * 4);
        int sz = ok ? 16 : 0;
        asm volatile("cp.async.cg.shared.global [%0], [%1], 16, %2;\n"
                     :: "r"(d1), "l"(g1), "r"(sz));
        asm volatile("cp.async.cg.shared.global [%0], [%1], 16, %2;\n"
                     :: "r"(d2), "l"(g2), "r"(sz));
    }
    asm volatile("cp.async.commit_group;\n");
    asm volatile("cp.async.wait_group 0;\n");
    __syncthreads();

    // ---- Phase 2: vertical conv, paired-field FFMA2 scatter ----
    for (int task = tid; task < IN_W * (TILE_H / 4); task += NTHREADS) {
        int c  = task % IN_W;              // logical column 0..73
        int j0 = (task / IN_W) * 4;
        const float* col1 = s1 + j0 * SSTRIDE + (c + 3);
        const float* col2 = s2 + j0 * SSTRIDE + (c + 3);

        ull A01[4], A23[4];
        #pragma unroll
        for (int m = 0; m < 4; m++) { A01[m] = 0ull; A23[m] = 0ull; }

        #pragma unroll
        for (int r = 0; r < 14; r++) {
            float x = col1[r * SSTRIDE];
            float y = col2[r * SSTRIDE];
            float xy   = x * y;
            float xxyy = fmaf(x, x, y * y);
            ull p01 = pack2(x, y);
            ull p23 = pack2(xxyy, xy);
            #pragma unroll
            for (int m = 0; m < 4; m++) {
                const int k = r - m;
                if (k >= 0 && k < 11) {         // compile-time resolved
                    A01[m] = fma2(p01, Wp[Widx(k)], A01[m]);
                    A23[m] = fma2(p23, Wp[Widx(k)], A23[m]);
                }
            }
        }
        #pragma unroll
        for (int m = 0; m < 4; m++) {
            int o = (j0 + m) * S2STRIDE + c;
            mid01[o] = A01[m];
            mid23[o] = A23[m];
        }
    }
    __syncthreads();

    // ---- Phase 3: plane-split horizontal conv (8 outputs per thread pair) ----
    const int p   = tid & 1;            // plane: 0 = (mu1,mu2), 1 = (xx+yy, xy)
    const int g   = (tid >> 1) & 7;     // 8-col group
    const int row = tid >> 4;           // 0..15
    const int c0  = g * 8;

    ull acc[8];
    #pragma unroll
    for (int i = 0; i < 8; i++) acc[i] = 0ull;
    {
        const ull* plane = p ? mid23 : mid01;
        const ulonglong2* ptr = reinterpret_cast<const ulonglong2*>(
            plane + row * S2STRIDE + c0);
        #pragma unroll
        for (int q = 0; q < 9; q++) {
            ulonglong2 u = ptr[q];
            #pragma unroll
            for (int h = 0; h < 2; h++) {
                const int j = 2 * q + h;
                const ull e = h ? u.y : u.x;
                #pragma unroll
                for (int i = 0; i < 8; i++) {
                    const int k = j - i;
                    if (k >= 0 && k < 11)
                        acc[i] = fma2(e, Wp[Widx(k)], acc[i]);
                }
            }
        }
    }

    // pair exchange: thread p gets the OTHER plane's accs for its 4 outputs
    ull r4[4];
    #pragma unroll
    for (int j = 0; j < 4; j++) {
        ull send = (p == 0) ? acc[4 + j] : acc[j];
        r4[j] = __shfl_xor_sync(0xFFFFFFFFu, send, 1);
    }

    // C1/C2 from global min/max (set by minmax_k earlier in the stream)
    float L = dec_f(g_minmax[1]) - dec_f(g_minmax[0]);
    if (L == 0.0f) L = 5.0f;
    const float c1v = 0.01f * L, c2v = 0.03f * L;
    const float C1 = c1v * c1v, C2 = c2v * c2v;

    float o4[4];
    #pragma unroll
    for (int i = 0; i < 4; i++) {
        ull mu_acc = (p == 0) ? acc[i] : r4[i];
        ull sq_acc = (p == 0) ? r4[i] : acc[4 + i];
        float mu1, mu2, sqc, xyc;
        unpack2(mu1, mu2, mu_acc);
        unpack2(sqc, xyc, sq_acc);
        float mu1s = mu1 * mu1, mu2s = mu2 * mu2, m12 = mu1 * mu2;
        float sqsum = sqc - mu1s - mu2s;   // sigma1_sq + sigma2_sq
        float s12   = xyc - m12;           // sigma12
        float num = (2.f * m12 + C1) * (2.f * s12 + C2);
        float den = (mu1s + mu2s + C1) * (sqsum + C2);
        o4[i] = __fdividef(num, den);
    }

    const int gy = by * TILE_H + row;
    const int gx = bx * TILE_W + c0 + 4 * p;
    float4* po = reinterpret_cast<float4*>(out + base + gy * IMG_W + gx);
    po[0] = make_float4(o4[0], o4[1], o4[2], o4[3]);

    // ---- epilogue: last-finishing block restores sentinels for next replay ----
    if (tid == 0) {
        __threadfence();                       // order g_minmax reads before counter
        unsigned d = atomicAdd(&g_done, 1u);
        if (d == (unsigned)(nblocks - 1)) {
            g_minmax[0] = 0xFFFFFFFFu;
            g_minmax[1] = 0u;
            g_done = 0u;
        }
    }
}

// ---------------- launch ----------------

extern "C" void kernel_launch(void* const* d_in, const int* in_sizes, int n_in,
                              void* d_out, int out_size)
{
    const float* img1 = (const float*)d_in[0];
    const float* img2 = (const float*)d_in[1];
    float* out = (float*)d_out;
    const int n = in_sizes[0];
    const int batch = n / (IMG_H * IMG_W);

    const int smem_bytes = (2 * IN_H * SSTRIDE) * (int)sizeof(float)
                         + (2 * TILE_H * S2STRIDE) * (int)sizeof(ull);
    cudaFuncSetAttribute(ssim_kernel, cudaFuncAttributeMaxDynamicSharedMemorySize, smem_bytes);

    minmax_k<<<1184, 256>>>((const float4*)img1, n / 4);

    dim3 grid(IMG_W / TILE_W, IMG_H / TILE_H, batch);
    ssim_kernel<<<grid, NTHREADS, smem_bytes>>>(img1, img2, out);
}

// round 11
// speedup vs baseline: 1.3237x; 1.2490x over previous
#include <cuda_runtime.h>
#include <cstdint>

#define IMG_H 512
#define IMG_W 512
#define TILE_W 64
#define TILE_H 16
#define HALO 5
#define IN_W (TILE_W + 2*HALO)   // 74 logical halo columns
#define IN_H (TILE_H + 2*HALO)   // 26
#define SSTRIDE 80               // padded smem row stride (floats)
#define NTHREADS 256
#define NFIELDS 4                // mu1, mu2, xx+yy, xy

// Normalized Gaussian taps: g[k] = exp(-(k - 11/2)^2 / (2*1.5^2)) / sum, k=0..10.
// Center at 5.5 => ASYMMETRIC: w[k] == w[11-k] for k>=1, w[0] unique smallest.
__host__ __device__ __forceinline__ constexpr float Wc(int k) {
    return (k == 0)            ? 3.2030000e-04f
         : (k == 1 || k == 10) ? 2.9556400e-03f
         : (k == 2 || k == 9 ) ? 1.7487660e-02f
         : (k == 3 || k == 8 ) ? 6.6342400e-02f
         : (k == 4 || k == 7 ) ? 1.6137290e-01f
         :                       2.5168140e-01f;   // k == 5 || k == 6
}

// ---------------- global min/max of img1 (encoded atomics, no init kernel) ----------------
// Sentinels restored by ssim_kernel's last-finishing block each launch.

__device__ unsigned g_minmax[2] = { 0xFFFFFFFFu, 0u };   // [0]=min slot, [1]=max slot
__device__ unsigned g_done = 0;

__device__ __forceinline__ unsigned enc_f(float f) {
    unsigned u = __float_as_uint(f);
    return (u & 0x80000000u) ? ~u : (u | 0x80000000u);
}
__device__ __forceinline__ float dec_f(unsigned u) {
    return (u & 0x80000000u) ? __uint_as_float(u ^ 0x80000000u) : __uint_as_float(~u);
}

__global__ void minmax_k(const float4* __restrict__ x, int n4) {
    float lo =  3.402823466e38f;
    float hi = -3.402823466e38f;
    for (int i = blockIdx.x * blockDim.x + threadIdx.x; i < n4; i += gridDim.x * blockDim.x) {
        float4 v = x[i];
        lo = fminf(lo, fminf(fminf(v.x, v.y), fminf(v.z, v.w)));
        hi = fmaxf(hi, fmaxf(fmaxf(v.x, v.y), fmaxf(v.z, v.w)));
    }
    #pragma unroll
    for (int s = 16; s > 0; s >>= 1) {
        lo = fminf(lo, __shfl_xor_sync(0xFFFFFFFFu, lo, s));
        hi = fmaxf(hi, __shfl_xor_sync(0xFFFFFFFFu, hi, s));
    }
    __shared__ float slo[8], shi[8];
    int w = threadIdx.x >> 5, l = threadIdx.x & 31;
    if (l == 0) { slo[w] = lo; shi[w] = hi; }
    __syncthreads();
    if (threadIdx.x == 0) {
        int nw = blockDim.x >> 5;
        for (int i = 1; i < nw; i++) { lo = fminf(lo, slo[i]); hi = fmaxf(hi, shi[i]); }
        atomicMin(&g_minmax[0], enc_f(lo));
        atomicMax(&g_minmax[1], enc_f(hi));
    }
}

// ---------------- fused separable SSIM kernel (R6 structure) ----------------
//
// One block = 64x16 output tile. smem = 37.1KB -> 6 blocks/SM.
// Phase 1: cp.async 16B zfill halo load.
// Phase 2: vertical 11-tap conv of 4 fields (mu1, mu2, xx+yy, xy), imm-FFMA scatter.
// Phase 3: horizontal 11-tap conv, conflict-free float4 smem loads (threads 16B
//          apart -> quarter-warp covers one 128B line), SSIM formula.
// Epilogue: last-finishing block restores g_minmax sentinels for next replay.

__global__ void __launch_bounds__(NTHREADS, 6)
ssim_kernel(const float* __restrict__ img1, const float* __restrict__ img2,
            float* __restrict__ out)
{
    extern __shared__ float smem[];
    float* s1  = smem;                      // IN_H * SSTRIDE
    float* s2  = smem + IN_H * SSTRIDE;
    float* mid = smem + 2 * IN_H * SSTRIDE; // NFIELDS * TILE_H * SSTRIDE

    const int bx = blockIdx.x, by = blockIdx.y, bz = blockIdx.z;
    const int tid = threadIdx.x;
    const int nblocks = (int)(gridDim.x * gridDim.y * gridDim.z);
    const size_t base = (size_t)bz * (IMG_H * IMG_W);
    const float* p1 = img1 + base;
    const float* p2 = img2 + base;

    // ---- Phase 1: cp.async halo load, zero-fill OOB granules ----
    const int gx_base = bx * TILE_W - 8;    // 16B-aligned; granules fully in/out
    const int gy_base = by * TILE_H - HALO;
    for (int idx = tid; idx < IN_H * 20; idx += NTHREADS) {
        int r  = idx / 20;
        int c4 = idx - r * 20;
        int gy = gy_base + r;
        int gx = gx_base + c4 * 4;
        bool ok = ((unsigned)gy < (unsigned)IMG_H) && ((unsigned)gx < (unsigned)IMG_W);
        int cgy = min(max(gy, 0), IMG_H - 1);
        int cgx = min(max(gx, 0), IMG_W - 4);
        const float* g1 = p1 + cgy * IMG_W + cgx;
        const float* g2 = p2 + cgy * IMG_W + cgx;
        unsigned d1 = (unsigned)__cvta_generic_to_shared(s1 + r * SSTRIDE + c4 * 4);
        unsigned d2 = (unsigned)__cvta_generic_to_shared(s2 + r * SSTRIDE + c4 * 4);
        int sz = ok ? 16 : 0;
        asm volatile("cp.async.cg.shared.global [%0], [%1], 16, %2;\n"
                     :: "r"(d1), "l"(g1), "r"(sz));
        asm volatile("cp.async.cg.shared.global [%0], [%1], 16, %2;\n"
                     :: "r"(d2), "l"(g2), "r"(sz));
    }
    asm volatile("cp.async.commit_group;\n");
    asm volatile("cp.async.wait_group 0;\n");
    __syncthreads();

    // ---- Phase 2: vertical conv, products-once + imm-FFMA scatter ----
    for (int task = tid; task < IN_W * (TILE_H / 4); task += NTHREADS) {
        int c  = task % IN_W;              // logical column 0..73
        int j0 = (task / IN_W) * 4;
        const float* col1 = s1 + j0 * SSTRIDE + (c + 3);
        const float* col2 = s2 + j0 * SSTRIDE + (c + 3);

        float A[4][NFIELDS];
        #pragma unroll
        for (int m = 0; m < 4; m++)
            #pragma unroll
            for (int f = 0; f < NFIELDS; f++)
                A[m][f] = 0.f;

        #pragma unroll
        for (int r = 0; r < 14; r++) {
            float x = col1[r * SSTRIDE];
            float y = col2[r * SSTRIDE];
            float xy   = x * y;
            float xxyy = fmaf(x, x, y * y);
            #pragma unroll
            for (int m = 0; m < 4; m++) {
                const int k = r - m;
                if (k >= 0 && k < 11) {      // compile-time resolved
                    const float w = Wc(k);   // literal -> imm-form FFMA
                    A[m][0] = fmaf(x,    w, A[m][0]);
                    A[m][1] = fmaf(y,    w, A[m][1]);
                    A[m][2] = fmaf(xxyy, w, A[m][2]);
                    A[m][3] = fmaf(xy,   w, A[m][3]);
                }
            }
        }
        #pragma unroll
        for (int m = 0; m < 4; m++) {
            int o = (j0 + m) * SSTRIDE + c;
            #pragma unroll
            for (int f = 0; f < NFIELDS; f++)
                mid[f * TILE_H * SSTRIDE + o] = A[m][f];
        }
    }
    __syncthreads();

    // ---- Phase 3: horizontal conv (4 outputs per thread) + SSIM formula ----
    const int row = tid >> 4;          // 0..15
    const int c0  = (tid & 15) * 4;    // 0,4,...,60

    float res[NFIELDS][4];
    #pragma unroll
    for (int f = 0; f < NFIELDS; f++) {
        float t[16];
        const float4* p = reinterpret_cast<const float4*>(
            mid + f * TILE_H * SSTRIDE + row * SSTRIDE + c0);
        #pragma unroll
        for (int q = 0; q < 4; q++) {
            float4 u = p[q];
            t[4*q+0] = u.x; t[4*q+1] = u.y; t[4*q+2] = u.z; t[4*q+3] = u.w;
        }
        #pragma unroll
        for (int i = 0; i < 4; i++) {
            float acc = 0.f;
            #pragma unroll
            for (int k = 0; k < 11; k++)
                acc = fmaf(t[i + k], Wc(k), acc);
            res[f][i] = acc;
        }
    }

    // C1/C2 from global min/max (set by minmax_k earlier in the stream)
    float L = dec_f(g_minmax[1]) - dec_f(g_minmax[0]);
    if (L == 0.0f) L = 5.0f;
    const float c1v = 0.01f * L, c2v = 0.03f * L;
    const float C1 = c1v * c1v, C2 = c2v * c2v;

    float o4[4];
    #pragma unroll
    for (int i = 0; i < 4; i++) {
        float mu1 = res[0][i], mu2 = res[1][i];
        float mu1s = mu1 * mu1, mu2s = mu2 * mu2, m12 = mu1 * mu2;
        float sqsum = res[2][i] - mu1s - mu2s;   // sigma1_sq + sigma2_sq
        float s12   = res[3][i] - m12;           // sigma12
        float num = (2.f * m12 + C1) * (2.f * s12 + C2);
        float den = (mu1s + mu2s + C1) * (sqsum + C2);
        o4[i] = __fdividef(num, den);
    }

    const int gy = by * TILE_H + row;
    const int gx = bx * TILE_W + c0;
    float4* po = reinterpret_cast<float4*>(out + base + gy * IMG_W + gx);
    po[0] = make_float4(o4[0], o4[1], o4[2], o4[3]);

    // ---- epilogue: last-finishing block restores sentinels for next replay ----
    if (tid == 0) {
        __threadfence();                       // order g_minmax reads before counter
        unsigned d = atomicAdd(&g_done, 1u);
        if (d == (unsigned)(nblocks - 1)) {
            g_minmax[0] = 0xFFFFFFFFu;
            g_minmax[1] = 0u;
            g_done = 0u;
        }
    }
}

// ---------------- launch ----------------

extern "C" void kernel_launch(void* const* d_in, const int* in_sizes, int n_in,
                              void* d_out, int out_size)
{
    const float* img1 = (const float*)d_in[0];
    const float* img2 = (const float*)d_in[1];
    float* out = (float*)d_out;
    const int n = in_sizes[0];
    const int batch = n / (IMG_H * IMG_W);

    const int smem_bytes = (2 * IN_H * SSTRIDE + NFIELDS * TILE_H * SSTRIDE) * (int)sizeof(float);
    cudaFuncSetAttribute(ssim_kernel, cudaFuncAttributeMaxDynamicSharedMemorySize, smem_bytes);

    minmax_k<<<1184, 256>>>((const float4*)img1, n / 4);

    dim3 grid(IMG_W / TILE_W, IMG_H / TILE_H, batch);
    ssim_kernel<<<grid, NTHREADS, smem_bytes>>>(img1, img2, out);
}

// round 12
// speedup vs baseline: 1.3252x; 1.0011x over previous
#include <cuda_runtime.h>
#include <cstdint>

#define IMG_H 512
#define IMG_W 512
#define TILE_W 64
#define TILE_H 16
#define HALO 5
#define IN_W (TILE_W + 2*HALO)   // 74 logical halo columns
#define IN_H (TILE_H + 2*HALO)   // 26
#define SSTRIDE 80               // s1/s2 row stride (floats)
#define MSTRIDE 77               // mid row stride in float4/ulonglong2 units (bank-skewed: 308 words ≡ 20 mod 32)
#define NTHREADS 256

typedef unsigned long long ull;

// Normalized Gaussian taps: g[k] = exp(-(k - 11/2)^2 / (2*1.5^2)) / sum, k=0..10.
// Center at 5.5 => ASYMMETRIC: w[k] == w[11-k] for k>=1, w[0] unique smallest.
__host__ __device__ __forceinline__ constexpr float Wc(int k) {
    return (k == 0)            ? 3.2030000e-04f
         : (k == 1 || k == 10) ? 2.9556400e-03f
         : (k == 2 || k == 9 ) ? 1.7487660e-02f
         : (k == 3 || k == 8 ) ? 6.6342400e-02f
         : (k == 4 || k == 7 ) ? 1.6137290e-01f
         :                       2.5168140e-01f;   // k == 5 || k == 6
}
__host__ __device__ __forceinline__ constexpr int Widx(int k) {
    return (k == 0)            ? 0
         : (k == 1 || k == 10) ? 1
         : (k == 2 || k == 9 ) ? 2
         : (k == 3 || k == 8 ) ? 3
         : (k == 4 || k == 7 ) ? 4
         :                       5;
}

// ---- f32x2 packed helpers ----
__device__ __forceinline__ ull pack2(float lo, float hi) {
    ull r;
    asm("mov.b64 %0, {%1, %2};" : "=l"(r) : "f"(lo), "f"(hi));
    return r;
}
__device__ __forceinline__ void unpack2(float& lo, float& hi, ull v) {
    asm("mov.b64 {%0, %1}, %2;" : "=f"(lo), "=f"(hi) : "l"(v));
}
__device__ __forceinline__ ull fma2(ull a, ull b, ull c) {
    ull d;
    asm("fma.rn.f32x2 %0, %1, %2, %3;" : "=l"(d) : "l"(a), "l"(b), "l"(c));
    return d;
}

// ---------------- global min/max of img1 (encoded atomics, no init kernel) ----------------
// Sentinels restored by ssim_kernel's last-finishing block each launch.

__device__ unsigned g_minmax[2] = { 0xFFFFFFFFu, 0u };
__device__ unsigned g_done = 0;

__device__ __forceinline__ unsigned enc_f(float f) {
    unsigned u = __float_as_uint(f);
    return (u & 0x80000000u) ? ~u : (u | 0x80000000u);
}
__device__ __forceinline__ float dec_f(unsigned u) {
    return (u & 0x80000000u) ? __uint_as_float(u ^ 0x80000000u) : __uint_as_float(~u);
}

__global__ void minmax_k(const float4* __restrict__ x, int n4) {
    float lo =  3.402823466e38f;
    float hi = -3.402823466e38f;
    for (int i = blockIdx.x * blockDim.x + threadIdx.x; i < n4; i += gridDim.x * blockDim.x) {
        float4 v = x[i];
        lo = fminf(lo, fminf(fminf(v.x, v.y), fminf(v.z, v.w)));
        hi = fmaxf(hi, fmaxf(fmaxf(v.x, v.y), fmaxf(v.z, v.w)));
    }
    #pragma unroll
    for (int s = 16; s > 0; s >>= 1) {
        lo = fminf(lo, __shfl_xor_sync(0xFFFFFFFFu, lo, s));
        hi = fmaxf(hi, __shfl_xor_sync(0xFFFFFFFFu, hi, s));
    }
    __shared__ float slo[8], shi[8];
    int w = threadIdx.x >> 5, l = threadIdx.x & 31;
    if (l == 0) { slo[w] = lo; shi[w] = hi; }
    __syncthreads();
    if (threadIdx.x == 0) {
        int nw = blockDim.x >> 5;
        for (int i = 1; i < nw; i++) { lo = fminf(lo, slo[i]); hi = fmaxf(hi, shi[i]); }
        atomicMin(&g_minmax[0], enc_f(lo));
        atomicMax(&g_minmax[1], enc_f(hi));
    }
}

// ---------------- fused separable SSIM kernel ----------------
//
// One block = 64x16 output tile. smem = 35.5KB -> 6 blocks/SM.
// mid = ONE plane of float4 per column: (mu1, mu2, xx+yy, xy) = 2 x f32x2.
// Phase 1: cp.async 16B zfill halo load.
// Phase 2: vertical 11-tap conv, FFMA2 scatter (88 fma2/task), STS.128 stores.
// Phase 3: row=tid&15, c0=(tid>>4)*4; 14 LDS.128/thread, conflict-free via
//          MSTRIDE=77 (row delta = 20 words mod 32 -> 8 lanes cover all banks);
//          88 fma2/thread, SSIM formula, float4 store.
// Epilogue: last-finishing block restores g_minmax sentinels for next replay.

__global__ void __launch_bounds__(NTHREADS, 6)
ssim_kernel(const float* __restrict__ img1, const float* __restrict__ img2,
            float* __restrict__ out)
{
    extern __shared__ float smem[];
    float* s1 = smem;                          // IN_H * SSTRIDE floats
    float* s2 = smem + IN_H * SSTRIDE;
    ulonglong2* midq = reinterpret_cast<ulonglong2*>(smem + 2 * IN_H * SSTRIDE); // TILE_H * MSTRIDE

    const int bx = blockIdx.x, by = blockIdx.y, bz = blockIdx.z;
    const int tid = threadIdx.x;
    const int nblocks = (int)(gridDim.x * gridDim.y * gridDim.z);
    const size_t base = (size_t)bz * (IMG_H * IMG_W);
    const float* p1 = img1 + base;
    const float* p2 = img2 + base;

    // packed duplicated weights
    ull Wp[6];
    #pragma unroll
    for (int j = 0; j < 6; j++) {
        const float wv = (j == 0) ? Wc(0) : (j == 1) ? Wc(1) : (j == 2) ? Wc(2)
                       : (j == 3) ? Wc(3) : (j == 4) ? Wc(4) : Wc(5);
        Wp[j] = pack2(wv, wv);
    }

    // ---- Phase 1: cp.async halo load, zero-fill OOB granules ----
    const int gx_base = bx * TILE_W - 8;    // 16B-aligned; granules fully in/out
    const int gy_base = by * TILE_H - HALO;
    for (int idx = tid; idx < IN_H * 20; idx += NTHREADS) {
        int r  = idx / 20;
        int c4 = idx - r * 20;
        int gy = gy_base + r;
        int gx = gx_base + c4 * 4;
        bool ok = ((unsigned)gy < (unsigned)IMG_H) && ((unsigned)gx < (unsigned)IMG_W);
        int cgy = min(max(gy, 0), IMG_H - 1);
        int cgx = min(max(gx, 0), IMG_W - 4);
        const float* g1 = p1 + cgy * IMG_W + cgx;
        const float* g2 = p2 + cgy * IMG_W + cgx;
        unsigned d1 = (unsigned)__cvta_generic_to_shared(s1 + r * SSTRIDE + c4 * 4);
        unsigned d2 = (unsigned)__cvta_generic_to_shared(s2 + r * SSTRIDE + c4 * 4);
        int sz = ok ? 16 : 0;
        asm volatile("cp.async.cg.shared.global [%0], [%1], 16, %2;\n"
                     :: "r"(d1), "l"(g1), "r"(sz));
        asm volatile("cp.async.cg.shared.global [%0], [%1], 16, %2;\n"
                     :: "r"(d2), "l"(g2), "r"(sz));
    }
    asm volatile("cp.async.commit_group;\n");
    asm volatile("cp.async.wait_group 0;\n");
    __syncthreads();

    // ---- Phase 2: vertical conv, paired-field FFMA2 scatter, STS.128 stores ----
    for (int task = tid; task < IN_W * (TILE_H / 4); task += NTHREADS) {
        int c  = task % IN_W;              // logical column 0..73
        int j0 = (task / IN_W) * 4;
        const float* col1 = s1 + j0 * SSTRIDE + (c + 3);
        const float* col2 = s2 + j0 * SSTRIDE + (c + 3);

        ull A01[4], A23[4];
        #pragma unroll
        for (int m = 0; m < 4; m++) { A01[m] = 0ull; A23[m] = 0ull; }

        #pragma unroll
        for (int r = 0; r < 14; r++) {
            float x = col1[r * SSTRIDE];
            float y = col2[r * SSTRIDE];
            ull p01 = pack2(x, y);
            ull p23 = pack2(fmaf(x, x, y * y), x * y);
            #pragma unroll
            for (int m = 0; m < 4; m++) {
                const int k = r - m;
                if (k >= 0 && k < 11) {         // compile-time resolved
                    A01[m] = fma2(p01, Wp[Widx(k)], A01[m]);
                    A23[m] = fma2(p23, Wp[Widx(k)], A23[m]);
                }
            }
        }
        #pragma unroll
        for (int m = 0; m < 4; m++) {
            ulonglong2 v;
            v.x = A01[m];
            v.y = A23[m];
            midq[(j0 + m) * MSTRIDE + c] = v;   // STS.128, lanes 16B apart
        }
    }
    __syncthreads();

    // ---- Phase 3: horizontal conv (4 outputs/thread) + SSIM formula ----
    const int row = tid & 15;          // consecutive lanes -> consecutive rows (conflict-free)
    const int c0  = (tid >> 4) * 4;    // 0,4,...,60

    ull acc01[4], acc23[4];
    #pragma unroll
    for (int i = 0; i < 4; i++) { acc01[i] = 0ull; acc23[i] = 0ull; }

    {
        const ulonglong2* ptr = midq + row * MSTRIDE + c0;
        #pragma unroll
        for (int q = 0; q < 14; q++) {
            ulonglong2 u = ptr[q];              // LDS.128: column c0+q, fields packed
            #pragma unroll
            for (int i = 0; i < 4; i++) {
                const int k = q - i;
                if (k >= 0 && k < 11) {
                    acc01[i] = fma2(u.x, Wp[Widx(k)], acc01[i]);
                    acc23[i] = fma2(u.y, Wp[Widx(k)], acc23[i]);
                }
            }
        }
    }

    // C1/C2 from global min/max (set by minmax_k earlier in the stream)
    float L = dec_f(g_minmax[1]) - dec_f(g_minmax[0]);
    if (L == 0.0f) L = 5.0f;
    const float c1v = 0.01f * L, c2v = 0.03f * L;
    const float C1 = c1v * c1v, C2 = c2v * c2v;

    float o4[4];
    #pragma unroll
    for (int i = 0; i < 4; i++) {
        float mu1, mu2, sqc, xyc;
        unpack2(mu1, mu2, acc01[i]);
        unpack2(sqc, xyc, acc23[i]);
        float mu1s = mu1 * mu1, mu2s = mu2 * mu2, m12 = mu1 * mu2;
        float sqsum = sqc - mu1s - mu2s;   // sigma1_sq + sigma2_sq
        float s12   = xyc - m12;           // sigma12
        float num = (2.f * m12 + C1) * (2.f * s12 + C2);
        float den = (mu1s + mu2s + C1) * (sqsum + C2);
        o4[i] = __fdividef(num, den);
    }

    const int gy = by * TILE_H + row;
    const int gx = bx * TILE_W + c0;
    float4* po = reinterpret_cast<float4*>(out + base + gy * IMG_W + gx);
    po[0] = make_float4(o4[0], o4[1], o4[2], o4[3]);

    // ---- epilogue: last-finishing block restores sentinels for next replay ----
    if (tid == 0) {
        __threadfence();                       // order g_minmax reads before counter
        unsigned d = atomicAdd(&g_done, 1u);
        if (d == (unsigned)(nblocks - 1)) {
            g_minmax[0] = 0xFFFFFFFFu;
            g_minmax[1] = 0u;
            g_done = 0u;
        }
    }
}

// ---------------- launch ----------------

extern "C" void kernel_launch(void* const* d_in, const int* in_sizes, int n_in,
                              void* d_out, int out_size)
{
    const float* img1 = (const float*)d_in[0];
    const float* img2 = (const float*)d_in[1];
    float* out = (float*)d_out;
    const int n = in_sizes[0];
    const int batch = n / (IMG_H * IMG_W);

    const int smem_bytes = (2 * IN_H * SSTRIDE) * (int)sizeof(float)
                         + (TILE_H * MSTRIDE) * (int)sizeof(ulonglong2);
    cudaFuncSetAttribute(ssim_kernel, cudaFuncAttributeMaxDynamicSharedMemorySize, smem_bytes);

    minmax_k<<<1184, 256>>>((const float4*)img1, n / 4);

    dim3 grid(IMG_W / TILE_W, IMG_H / TILE_H, batch);
    ssim_kernel<<<grid, NTHREADS, smem_bytes>>>(img1, img2, out);
}